// round 15
// baseline (speedup 1.0000x reference)
#include <cuda_runtime.h>
#include <cuda_bf16.h>
#include <cuda_fp16.h>
#include <cstdint>

// Problem constants
#define BB   16
#define NN   1024
#define DD   128
#define EE   16384
#define AA   64
#define DIAM 3
#define CH   64           // edge chunks for CSR build
#define CE   (EE / CH)    // 256 edges per chunk

// ---------------- device scratch (no allocations allowed) ----------------
__device__ float g_h[BB * NN * DD];             // node state fp32
__device__ __half g_hh[BB * NN * DD];           // h hi (fp16)
__device__ __half g_hl[BB * NN * DD];           // h lo (fp16 residual)
__device__ __half g_msg[BB * NN * 256];         // [hs|ht] per node, fp16
__device__ __half g_gh[BB * NN * 384];          // gh per node, fp16
__device__ __half g_aggh[BB * NN * DD];         // agg hi
__device__ __half g_aggl[BB * NN * DD];         // agg lo
__device__ float g_ef[BB * EE];                 // edge scalars, CSR slot order
__device__ __half g_Wb[640 * 128];              // packed big weight, fp16, [n][k]
__device__ __half g_Wih[384 * 128];             // W_ih fp16, [n][k]
__device__ float g_bias1[640];                  // [0,0,b_hh]
__device__ int   g_ccnt[CH * NN];
__device__ int   g_deg[NN];
__device__ int   g_off[NN + 1];
__device__ int   g_eid[EE];
__device__ int   g_esrc[EE];
__device__ float g_part[BB * 16 * DD];

__device__ __forceinline__ float selu_f(float x) {
    const float sc = 1.0507009873554805f, al = 1.6732632423543772f;
    return x > 0.f ? sc * x : sc * al * (__expf(x) - 1.f);
}

// ---------------- merged setup: weight pack + initial h convert ----------------
__global__ void k_prep(const float* __restrict__ Wmsg, const float* __restrict__ Whh,
                       const float* __restrict__ bhh, const float* __restrict__ Wih,
                       const float* __restrict__ nf) {
    int t = blockIdx.x * blockDim.x + threadIdx.x;
    if (t < 640 * 128) {
        int n = t >> 7, k = t & 127;
        float v;
        if (n < 128)       v = Wmsg[k * 128 + n];                 // src part
        else if (n < 256)  v = Wmsg[(128 + k) * 128 + (n - 128)]; // tgt part
        else               v = Whh[(n - 256) * 128 + k];          // W_hh^T
        g_Wb[t] = __float2half(v);
    }
    if (t < 384 * 128) g_Wih[t] = __float2half(Wih[t]);  // [384][128] == [n][k]
    if (t < 640) g_bias1[t] = (t < 256) ? 0.f : bhh[t - 256];
    if (t < BB * NN * DD) {
        float v = nf[t];
        __half hi = __float2half(v);
        g_hh[t] = hi;
        g_hl[t] = __float2half(v - __half2float(hi));
    }
}

// ---- CSR build: chunked histogram (deterministic stable order) ----
__global__ void k_cnt(const int* __restrict__ tgt) {  // grid CH, block 256
    __shared__ int c[NN];
    for (int i = threadIdx.x; i < NN; i += 256) c[i] = 0;
    __syncthreads();
    int e = blockIdx.x * CE + threadIdx.x;
    atomicAdd(&c[tgt[e]], 1);
    __syncthreads();
    for (int i = threadIdx.x; i < NN; i += 256) g_ccnt[blockIdx.x * NN + i] = c[i];
}

__global__ void k_tot() {  // grid 8, block 128
    int n = blockIdx.x * 128 + threadIdx.x;
    int s = 0;
#pragma unroll
    for (int c = 0; c < CH; ++c) s += g_ccnt[c * NN + n];
    g_deg[n] = s;
}

__global__ void k_scanx() {  // 1 block, 1024 threads: shfl 2-level scan
    __shared__ int wsum[32];
    int n = threadIdx.x, lane = n & 31, w = n >> 5;
    int v = g_deg[n];
    int sc = v;
#pragma unroll
    for (int o = 1; o < 32; o <<= 1) {
        int x = __shfl_up_sync(0xffffffffu, sc, o);
        if (lane >= o) sc += x;
    }
    if (lane == 31) wsum[w] = sc;
    __syncthreads();
    if (w == 0) {
        int s = wsum[lane];
#pragma unroll
        for (int o = 1; o < 32; o <<= 1) {
            int x = __shfl_up_sync(0xffffffffu, s, o);
            if (lane >= o) s += x;
        }
        wsum[lane] = s;
    }
    __syncthreads();
    int base = (w > 0) ? wsum[w - 1] : 0;
    g_off[n + 1] = base + sc;
    if (n == 0) g_off[0] = 0;
}

__global__ void k_offk() {  // grid 8, block 128
    int n = blockIdx.x * 128 + threadIdx.x;
    int run = g_off[n];
#pragma unroll
    for (int c = 0; c < CH; ++c) {
        int v = g_ccnt[c * NN + n];
        g_ccnt[c * NN + n] = run;
        run += v;
    }
}

__global__ void k_fill(const int* __restrict__ tgt, const int* __restrict__ src) {
    __shared__ int ctr[NN];
    int lane = threadIdx.x;
    int chunk = blockIdx.x;
    for (int i = lane; i < NN; i += 32) ctr[i] = g_ccnt[chunk * NN + i];
    __syncwarp();
    for (int r = 0; r < CE / 32; ++r) {
        int e = chunk * CE + r * 32 + lane;
        int t = tgt[e];
        unsigned mask = __match_any_sync(0xffffffffu, t);
        int leader = __ffs(mask) - 1;
        int rank = __popc(mask & ((1u << lane) - 1u));
        int base = 0;
        if (lane == leader) { base = ctr[t]; ctr[t] = base + __popc(mask); }
        base = __shfl_sync(0xffffffffu, base, leader);
        g_eid[base + rank] = e;
        g_esrc[base + rank] = src[e];
        __syncwarp();
    }
}

// gather edge scalars into CSR slot order (after k_fill)
__global__ void k_ef(const float* __restrict__ edge, const int* __restrict__ src,
                     const int* __restrict__ tgt) {
    int t = blockIdx.x * blockDim.x + threadIdx.x;
    if (t < BB * EE) {
        int b = t / EE, slot = t % EE;
        int e = g_eid[slot];
        g_ef[t] = edge[(size_t)b * NN * NN + (size_t)src[e] * NN + tgt[e]];
    }
}

// ---------------- shared GEMM helpers ----------------
#define SROW 136                          // padded row in fp16 elems
#define MPAN 512                          // 16384 rows / 32

__device__ __forceinline__ void cp16(uint32_t dst, const void* src) {
    asm volatile("cp.async.cg.shared.global [%0], [%1], 16;" :: "r"(dst), "l"(src));
}
__device__ __forceinline__ void ldsm4(uint32_t& r0, uint32_t& r1, uint32_t& r2, uint32_t& r3,
                                      uint32_t addr) {
    asm volatile("ldmatrix.sync.aligned.m8n8.x4.shared.b16 {%0,%1,%2,%3},[%4];"
                 : "=r"(r0), "=r"(r1), "=r"(r2), "=r"(r3) : "r"(addr));
}
__device__ __forceinline__ void mma_f16(float* d, const uint32_t* a, const uint32_t* b) {
    asm volatile(
        "mma.sync.aligned.m16n8k16.row.col.f32.f16.f16.f32 "
        "{%0,%1,%2,%3},{%4,%5,%6,%7},{%8,%9},{%0,%1,%2,%3};"
        : "+f"(d[0]), "+f"(d[1]), "+f"(d[2]), "+f"(d[3])
        : "r"(a[0]), "r"(a[1]), "r"(a[2]), "r"(a[3]), "r"(b[0]), "r"(b[1]));
}

// ---------------- gemm0: persistent weight-stationary split-fp16 HMMA ----------------
// cols 0..255 -> g_msg (fp16); cols 256..639 -> g_gh (fp16). 3 CTAs/SM.
#define B_H 0
#define A_BASE0 (128 * SROW)
#define MM_SMEM ((128 + 2 * 64) * SROW * 2)   // 69632 bytes

__global__ __launch_bounds__(256, 3) void k_mm0(const __half* __restrict__ Ahg,
                                                const __half* __restrict__ Alg,
                                                const __half* __restrict__ Bg,
                                                const float* __restrict__ bias,
                                                __half* __restrict__ Cm,
                                                __half* __restrict__ Cg) {
    extern __shared__ char smraw[];
    const int tid = threadIdx.x;
    const int bn = blockIdx.x;
    const int step = gridDim.y;
    const int lane = tid & 31, w = tid >> 5;
    const int wm = w >> 2, wn = w & 3;       // warp grid 2(m) x 4(n)

    uint32_t sbase = (uint32_t)__cvta_generic_to_shared(smraw);

    const __half* Bo = Bg + (size_t)(bn * 128) * 128;
#pragma unroll
    for (int i = 0; i < 8; ++i) {
        int idx = tid + i * 256;
        int row = idx >> 4, c8 = (idx & 15) * 8;
        cp16(sbase + (uint32_t)(row * SROW + c8) * 2, Bo + (size_t)row * 128 + c8);
    }

    auto loadA = [&](int bm, int buf) {
        const __half* Aho = Ahg + (size_t)(bm * 32) * 128;
        const __half* Alo = Alg + (size_t)(bm * 32) * 128;
        uint32_t ab = sbase + (uint32_t)(A_BASE0 + buf * 64 * SROW) * 2;
#pragma unroll
        for (int i = 0; i < 2; ++i) {
            int idx = tid + i * 256;
            int row = idx >> 4, c8 = (idx & 15) * 8;
            uint32_t so = (uint32_t)(row * SROW + c8) * 2;
            size_t g = (size_t)row * 128 + c8;
            cp16(ab + so, Aho + g);
            cp16(ab + (uint32_t)(32 * SROW) * 2 + so, Alo + g);
        }
    };

    const int bm0 = blockIdx.y;
    loadA(bm0, 0);
    asm volatile("cp.async.commit_group;" ::: "memory");

    const int grp = lane >> 2, qp = lane & 3;
    float2 bv[4];
#pragma unroll
    for (int nt = 0; nt < 4; ++nt) {
        int col = bn * 128 + wn * 32 + nt * 8 + qp * 2;
        bv[nt] = *(const float2*)(bias + col);
    }

    const int arow = wm * 16 + (lane & 15);
    const int akof = (lane >> 4) << 3;
    const int bnrow = wn * 32 + ((lane >> 4) << 3) + (lane & 7);
    const int bkof = ((lane >> 3) & 1) << 3;

    int buf = 0;
    for (int bm = bm0; bm < MPAN; bm += step) {
        int nxt = bm + step;
        if (nxt < MPAN) {
            loadA(nxt, buf ^ 1);
            asm volatile("cp.async.commit_group;" ::: "memory");
            asm volatile("cp.async.wait_group 1;" ::: "memory");
        } else {
            asm volatile("cp.async.wait_group 0;" ::: "memory");
        }
        __syncthreads();

        uint32_t abase = sbase + (uint32_t)(A_BASE0 + buf * 64 * SROW) * 2;
        uint32_t lbase = abase + (uint32_t)(32 * SROW) * 2;

        float acc[4][4];
#pragma unroll
        for (int nt = 0; nt < 4; ++nt)
#pragma unroll
            for (int q = 0; q < 4; ++q) acc[nt][q] = 0.f;

        uint32_t ah[2][4], al[2][4], bh[2][2][4];
        auto ldfr = [&](int ks, int fb) {
            int k0 = ks * 16;
            uint32_t aoff = (uint32_t)(arow * SROW + k0 + akof) * 2;
            ldsm4(ah[fb][0], ah[fb][1], ah[fb][2], ah[fb][3], abase + aoff);
            ldsm4(al[fb][0], al[fb][1], al[fb][2], al[fb][3], lbase + aoff);
#pragma unroll
            for (int np = 0; np < 2; ++np) {
                uint32_t off = (uint32_t)((bnrow + np * 16) * SROW + k0 + bkof) * 2;
                ldsm4(bh[fb][np][0], bh[fb][np][1], bh[fb][np][2], bh[fb][np][3],
                      sbase + off);
            }
        };

        ldfr(0, 0);
#pragma unroll
        for (int ks = 0; ks < 8; ++ks) {
            int fb = ks & 1;
            if (ks < 7) ldfr(ks + 1, fb ^ 1);
#pragma unroll
            for (int nt = 0; nt < 4; ++nt) {
                const uint32_t* bhp = &bh[fb][nt >> 1][(nt & 1) * 2];
                mma_f16(acc[nt], ah[fb], bhp);
                mma_f16(acc[nt], al[fb], bhp);
            }
        }

        int row = bm * 32 + wm * 16 + grp;
        if (bn < 2) {
#pragma unroll
            for (int nt = 0; nt < 4; ++nt) {
                int col = bn * 128 + wn * 32 + nt * 8 + qp * 2;
                __half2 v0 = __floats2half2_rn(acc[nt][0] + bv[nt].x, acc[nt][1] + bv[nt].y);
                __half2 v1 = __floats2half2_rn(acc[nt][2] + bv[nt].x, acc[nt][3] + bv[nt].y);
                *(__half2*)(Cm + (size_t)row * 256 + col) = v0;
                *(__half2*)(Cm + (size_t)(row + 8) * 256 + col) = v1;
            }
        } else {
#pragma unroll
            for (int nt = 0; nt < 4; ++nt) {
                int col = bn * 128 + wn * 32 + nt * 8 + qp * 2 - 256;
                __half2 v0 = __floats2half2_rn(acc[nt][0] + bv[nt].x, acc[nt][1] + bv[nt].y);
                __half2 v1 = __floats2half2_rn(acc[nt][2] + bv[nt].x, acc[nt][3] + bv[nt].y);
                *(__half2*)(Cg + (size_t)row * 384 + col) = v0;
                *(__half2*)(Cg + (size_t)(row + 8) * 384 + col) = v1;
            }
        }
        __syncthreads();
        buf ^= 1;
    }
}

// ---------------- fused gemm1 + GRU ----------------
// gi = (aggh+aggl) @ Wih^T + bih computed with gate-aligned warp mapping:
// warp (wm, wn) covers rows wm*16.., cols wn*32..+32 within EACH gate chunk,
// so every thread owns its (i_r, i_z, i_n) triple -> thread-local GRU epilogue.
// Full 384-row B panel resident (98KB) + double-buffered 32-row A panels.
#define A_BASE1 (384 * SROW)
#define MM1_SMEM ((384 + 2 * 64) * SROW * 2)   // 139264 bytes, 1 CTA/SM

__global__ __launch_bounds__(256) void k_mm1gru(const __half* __restrict__ Ahg,
                                                const __half* __restrict__ Alg,
                                                const __half* __restrict__ Bg,
                                                const float* __restrict__ bih,
                                                const float* __restrict__ hprev) {
    extern __shared__ char smraw[];
    const int tid = threadIdx.x;
    const int step = gridDim.x;
    const int lane = tid & 31, w = tid >> 5;
    const int wm = w >> 2, wn = w & 3;       // warp grid 2(m) x 4(n)

    uint32_t sbase = (uint32_t)__cvta_generic_to_shared(smraw);

    // resident B: all 384 gate rows x 128 k
#pragma unroll
    for (int i = 0; i < 24; ++i) {
        int idx = tid + i * 256;
        int row = idx >> 4, c8 = (idx & 15) * 8;
        cp16(sbase + (uint32_t)(row * SROW + c8) * 2, Bg + (size_t)row * 128 + c8);
    }

    auto loadA = [&](int bm, int buf) {
        const __half* Aho = Ahg + (size_t)(bm * 32) * 128;
        const __half* Alo = Alg + (size_t)(bm * 32) * 128;
        uint32_t ab = sbase + (uint32_t)(A_BASE1 + buf * 64 * SROW) * 2;
#pragma unroll
        for (int i = 0; i < 2; ++i) {
            int idx = tid + i * 256;
            int row = idx >> 4, c8 = (idx & 15) * 8;
            uint32_t so = (uint32_t)(row * SROW + c8) * 2;
            size_t g = (size_t)row * 128 + c8;
            cp16(ab + so, Aho + g);
            cp16(ab + (uint32_t)(32 * SROW) * 2 + so, Alo + g);
        }
    };

    const int bm0 = blockIdx.x;
    loadA(bm0, 0);
    asm volatile("cp.async.commit_group;" ::: "memory");

    const int grp = lane >> 2, qp = lane & 3;
    float2 bi[3][4];
#pragma unroll
    for (int g = 0; g < 3; ++g)
#pragma unroll
        for (int nt = 0; nt < 4; ++nt)
            bi[g][nt] = *(const float2*)(bih + g * 128 + wn * 32 + nt * 8 + qp * 2);

    const int arow = wm * 16 + (lane & 15);
    const int akof = (lane >> 4) << 3;
    const int bnr = wn * 32 + ((lane >> 4) << 3) + (lane & 7);
    const int bkof = ((lane >> 3) & 1) << 3;

    int buf = 0;
    for (int bm = bm0; bm < MPAN; bm += step) {
        int nxt = bm + step;
        if (nxt < MPAN) {
            loadA(nxt, buf ^ 1);
            asm volatile("cp.async.commit_group;" ::: "memory");
            asm volatile("cp.async.wait_group 1;" ::: "memory");
        } else {
            asm volatile("cp.async.wait_group 0;" ::: "memory");
        }
        __syncthreads();

        uint32_t abase = sbase + (uint32_t)(A_BASE1 + buf * 64 * SROW) * 2;
        uint32_t lbase = abase + (uint32_t)(32 * SROW) * 2;

        float acc[3][4][4];
#pragma unroll
        for (int g = 0; g < 3; ++g)
#pragma unroll
            for (int nt = 0; nt < 4; ++nt)
#pragma unroll
                for (int q = 0; q < 4; ++q) acc[g][nt][q] = 0.f;

#pragma unroll
        for (int ks = 0; ks < 8; ++ks) {
            int k0 = ks * 16;
            uint32_t ah[4], al[4], bh[3][2][4];
            uint32_t aoff = (uint32_t)(arow * SROW + k0 + akof) * 2;
            ldsm4(ah[0], ah[1], ah[2], ah[3], abase + aoff);
            ldsm4(al[0], al[1], al[2], al[3], lbase + aoff);
#pragma unroll
            for (int g = 0; g < 3; ++g)
#pragma unroll
                for (int np = 0; np < 2; ++np) {
                    int brow = g * 128 + bnr + np * 16;
                    uint32_t off = (uint32_t)(brow * SROW + k0 + bkof) * 2;
                    ldsm4(bh[g][np][0], bh[g][np][1], bh[g][np][2], bh[g][np][3],
                          sbase + off);
                }
#pragma unroll
            for (int g = 0; g < 3; ++g)
#pragma unroll
                for (int nt = 0; nt < 4; ++nt) {
                    const uint32_t* bhp = &bh[g][nt >> 1][(nt & 1) * 2];
                    mma_f16(acc[g][nt], ah, bhp);
                    mma_f16(acc[g][nt], al, bhp);
                }
        }

        // ---- thread-local GRU epilogue ----
#pragma unroll
        for (int rr = 0; rr < 2; ++rr) {
            int row = bm * 32 + wm * 16 + grp + rr * 8;
            const __half* ghr = g_gh + (size_t)row * 384;
            const float* hpr = hprev + (size_t)row * 128;
            float* ho = g_h + (size_t)row * 128;
            __half* hho = g_hh + (size_t)row * 128;
            __half* hlo = g_hl + (size_t)row * 128;
#pragma unroll
            for (int nt = 0; nt < 4; ++nt) {
                int col = wn * 32 + nt * 8 + qp * 2;
                float2 hr2 = __half22float2(*(const __half2*)(ghr + col));
                float2 hz2 = __half22float2(*(const __half2*)(ghr + 128 + col));
                float2 hn2 = __half22float2(*(const __half2*)(ghr + 256 + col));
                float2 hv = *(const float2*)(hpr + col);
                float outv[2];
                __half hi2[2], lo2[2];
#pragma unroll
                for (int j = 0; j < 2; ++j) {
                    int qa = rr * 2 + j;
                    float ir = acc[0][nt][qa] + (j ? bi[0][nt].y : bi[0][nt].x);
                    float iz = acc[1][nt][qa] + (j ? bi[1][nt].y : bi[1][nt].x);
                    float in_ = acc[2][nt][qa] + (j ? bi[2][nt].y : bi[2][nt].x);
                    float hr = j ? hr2.y : hr2.x;
                    float hz = j ? hz2.y : hz2.x;
                    float hn = j ? hn2.y : hn2.x;
                    float hvj = j ? hv.y : hv.x;
                    float r = 1.f / (1.f + __expf(-(ir + hr)));
                    float z = 1.f / (1.f + __expf(-(iz + hz)));
                    float nv = tanhf(in_ + r * hn);
                    float hnew = (1.f - z) * nv + z * hvj;
                    outv[j] = hnew;
                    hi2[j] = __float2half(hnew);
                    lo2[j] = __float2half(hnew - __half2float(hi2[j]));
                }
                *(float2*)(ho + col) = make_float2(outv[0], outv[1]);
                *(uint32_t*)(hho + col) = *(uint32_t*)hi2;
                *(uint32_t*)(hlo + col) = *(uint32_t*)lo2;
            }
        }
        __syncthreads();
        buf ^= 1;
    }
}

// ---------------- fused edge message + deterministic aggregation (fp16 gathers) ----------------
__device__ __forceinline__ float4 h4tof4(uint2 u) {
    __half2 a = *(__half2*)&u.x, b = *(__half2*)&u.y;
    float2 fa = __half22float2(a), fb = __half22float2(b);
    return make_float4(fa.x, fa.y, fb.x, fb.y);
}

__global__ __launch_bounds__(256) void k_edge(const float* __restrict__ Wmsg,
                                              const float* __restrict__ bmsg) {
    int lane = threadIdx.x & 31;
    int nl = threadIdx.x >> 5;            // 8 nodes per block
    int n = blockIdx.x * 8 + nl;
    int b = blockIdx.y;
    float4 we = *(const float4*)(Wmsg + 256 * 128 + lane * 4);
    float4 bm = *(const float4*)(bmsg + lane * 4);
    const __half* msgb = g_msg + (size_t)b * NN * 256;
    float4 ht = h4tof4(*(const uint2*)(msgb + (size_t)n * 256 + 128 + lane * 4));
    float4 base = {ht.x + bm.x, ht.y + bm.y, ht.z + bm.z, ht.w + bm.w};
    const float* efb = g_ef + (size_t)b * EE;
    int s0 = g_off[n], s1 = g_off[n + 1];
    float4 acc = {0.f, 0.f, 0.f, 0.f};
    int s = s0;
    for (; s + 4 <= s1; s += 4) {
        int sr0 = g_esrc[s], sr1 = g_esrc[s + 1], sr2 = g_esrc[s + 2], sr3 = g_esrc[s + 3];
        float e0 = efb[s], e1 = efb[s + 1], e2 = efb[s + 2], e3 = efb[s + 3];
        float4 h0 = h4tof4(*(const uint2*)(msgb + (size_t)sr0 * 256 + lane * 4));
        float4 h1 = h4tof4(*(const uint2*)(msgb + (size_t)sr1 * 256 + lane * 4));
        float4 h2 = h4tof4(*(const uint2*)(msgb + (size_t)sr2 * 256 + lane * 4));
        float4 h3 = h4tof4(*(const uint2*)(msgb + (size_t)sr3 * 256 + lane * 4));
        acc.x += selu_f(h0.x + base.x + e0 * we.x) + selu_f(h1.x + base.x + e1 * we.x)
               + selu_f(h2.x + base.x + e2 * we.x) + selu_f(h3.x + base.x + e3 * we.x);
        acc.y += selu_f(h0.y + base.y + e0 * we.y) + selu_f(h1.y + base.y + e1 * we.y)
               + selu_f(h2.y + base.y + e2 * we.y) + selu_f(h3.y + base.y + e3 * we.y);
        acc.z += selu_f(h0.z + base.z + e0 * we.z) + selu_f(h1.z + base.z + e1 * we.z)
               + selu_f(h2.z + base.z + e2 * we.z) + selu_f(h3.z + base.z + e3 * we.z);
        acc.w += selu_f(h0.w + base.w + e0 * we.w) + selu_f(h1.w + base.w + e1 * we.w)
               + selu_f(h2.w + base.w + e2 * we.w) + selu_f(h3.w + base.w + e3 * we.w);
    }
    for (; s < s1; ++s) {
        int sr0 = g_esrc[s];
        float e0 = efb[s];
        float4 h0 = h4tof4(*(const uint2*)(msgb + (size_t)sr0 * 256 + lane * 4));
        acc.x += selu_f(h0.x + base.x + e0 * we.x);
        acc.y += selu_f(h0.y + base.y + e0 * we.y);
        acc.z += selu_f(h0.z + base.z + e0 * we.z);
        acc.w += selu_f(h0.w + base.w + e0 * we.w);
    }
    size_t o = ((size_t)(b * NN + n)) * DD + lane * 4;
    float a4[4] = {acc.x, acc.y, acc.z, acc.w};
    __half hi4[4], lo4[4];
#pragma unroll
    for (int j = 0; j < 4; ++j) {
        hi4[j] = __float2half(a4[j]);
        lo4[j] = __float2half(a4[j] - __half2float(hi4[j]));
    }
    *(uint2*)(g_aggh + o) = *(uint2*)hi4;
    *(uint2*)(g_aggl + o) = *(uint2*)lo4;
}

// ---------------- pooling + readout head ----------------
__global__ void k_pool() {
    int c = blockIdx.x, b = blockIdx.y, d = threadIdx.x;
    const float* hb = g_h + ((size_t)b * NN + c * 64) * DD + d;
    float s = 0.f;
#pragma unroll 8
    for (int n = 0; n < 64; ++n) s += hb[(size_t)n * DD];
    g_part[(b * 16 + c) * DD + d] = s;
}

__global__ void k_head(const float* __restrict__ Wr1, const float* __restrict__ br1,
                       const float* __restrict__ Wr2, const float* __restrict__ br2,
                       const float* __restrict__ Wpol, const float* __restrict__ bpol,
                       float* __restrict__ out) {
    int b = blockIdx.x, d = threadIdx.x;
    __shared__ float p[128], q[128];
    float s = 0.f;
#pragma unroll
    for (int c = 0; c < 16; ++c) s += g_part[(b * 16 + c) * DD + d];
    p[d] = s;
    __syncthreads();
    float y = br1[d];
#pragma unroll 8
    for (int k = 0; k < 128; ++k) y = fmaf(p[k], Wr1[k * 128 + d], y);
    q[d] = selu_f(y);
    __syncthreads();
    y = br2[d];
#pragma unroll 8
    for (int k = 0; k < 128; ++k) y = fmaf(q[k], Wr2[k * 128 + d], y);
    float p2 = selu_f(y);
    __syncthreads();
    p[d] = p2;
    __syncthreads();
    if (d < 64) {
        float o = bpol[d];
#pragma unroll 8
        for (int k = 0; k < 128; ++k) o = fmaf(p[k], Wpol[k * 64 + d], o);
        out[b * 64 + d] = o;
    }
}

// ---------------- launch ----------------
extern "C" void kernel_launch(void* const* d_in, const int* in_sizes, int n_in,
                              void* d_out, int out_size) {
    const float* nf   = (const float*)d_in[0];
    const float* edge = (const float*)d_in[1];
    const int*   src  = (const int*)d_in[2];
    const int*   tgt  = (const int*)d_in[3];
    const float* Wmsg = (const float*)d_in[4];
    const float* bmsg = (const float*)d_in[5];
    const float* Wih  = (const float*)d_in[6];
    const float* Whh  = (const float*)d_in[7];
    const float* bih  = (const float*)d_in[8];
    const float* bhh  = (const float*)d_in[9];
    const float* Wr1  = (const float*)d_in[10];
    const float* br1  = (const float*)d_in[11];
    const float* Wr2  = (const float*)d_in[12];
    const float* br2  = (const float*)d_in[13];
    const float* Wpol = (const float*)d_in[14];
    const float* bpol = (const float*)d_in[15];
    float* out = (float*)d_out;

    float *g_h_p, *g_bias1_p;
    __half *gh_p, *msg_p, *wb_p, *wih_p, *hh_p, *hl_p, *aggh_p, *aggl_p;
    cudaGetSymbolAddress((void**)&g_h_p, g_h);
    cudaGetSymbolAddress((void**)&gh_p, g_gh);
    cudaGetSymbolAddress((void**)&g_bias1_p, g_bias1);
    cudaGetSymbolAddress((void**)&msg_p, g_msg);
    cudaGetSymbolAddress((void**)&wb_p, g_Wb);
    cudaGetSymbolAddress((void**)&wih_p, g_Wih);
    cudaGetSymbolAddress((void**)&hh_p, g_hh);
    cudaGetSymbolAddress((void**)&hl_p, g_hl);
    cudaGetSymbolAddress((void**)&aggh_p, g_aggh);
    cudaGetSymbolAddress((void**)&aggl_p, g_aggl);

    cudaFuncSetAttribute((const void*)k_mm0,
                         cudaFuncAttributeMaxDynamicSharedMemorySize, MM_SMEM);
    cudaFuncSetAttribute((const void*)k_mm1gru,
                         cudaFuncAttributeMaxDynamicSharedMemorySize, MM1_SMEM);

    // launch index 3 == first k_mm0 (profiled)
    k_prep<<<(BB * NN * DD + 255) / 256, 256>>>(Wmsg, Whh, bhh, Wih, nf);
    k_cnt<<<CH, 256>>>(tgt);
    k_tot<<<8, 128>>>();
    k_mm0<<<dim3(5, 88), 256, MM_SMEM>>>(hh_p, hl_p, wb_p, g_bias1_p, msg_p, gh_p);
    k_scanx<<<1, NN>>>();
    k_offk<<<8, 128>>>();
    k_fill<<<CH, 32>>>(tgt, src);
    k_ef<<<(BB * EE + 255) / 256, 256>>>(edge, src, tgt);

    for (int it = 0; it < DIAM; ++it) {
        if (it > 0)
            k_mm0<<<dim3(5, 88), 256, MM_SMEM>>>(hh_p, hl_p, wb_p, g_bias1_p, msg_p, gh_p);
        k_edge<<<dim3(NN / 8, BB), 256>>>(Wmsg, bmsg);
        k_mm1gru<<<128, 256, MM1_SMEM>>>(aggh_p, aggl_p, wih_p, bih,
                                         it == 0 ? nf : g_h_p);
    }

    k_pool<<<dim3(16, BB), 128>>>();
    k_head<<<BB, 128>>>(Wr1, br1, Wr2, br2, Wpol, bpol, out);
}

// round 16
// speedup vs baseline: 1.0645x; 1.0645x over previous
#include <cuda_runtime.h>
#include <cuda_bf16.h>
#include <cuda_fp16.h>
#include <cstdint>

// Problem constants
#define BB   16
#define NN   1024
#define DD   128
#define EE   16384
#define AA   64
#define DIAM 3
#define CH   64           // edge chunks for CSR build
#define CE   (EE / CH)    // 256 edges per chunk

// ---------------- device scratch (no allocations allowed) ----------------
__device__ float g_h[BB * NN * DD];             // node state fp32
__device__ __half g_hh[BB * NN * DD];           // h hi (fp16)
__device__ __half g_hl[BB * NN * DD];           // h lo (fp16 residual)
__device__ __half g_msg[BB * NN * 256];         // [hs|ht] per node, fp16
__device__ __half g_gh[BB * NN * 384];          // gh per node, fp16
__device__ __half g_aggh[BB * NN * DD];         // agg hi
__device__ __half g_aggl[BB * NN * DD];         // agg lo
__device__ __half g_gi[BB * NN * 384];          // gi = agg@Wih^T, fp16
__device__ float g_ef[BB * EE];                 // edge scalars, CSR slot order
__device__ __half g_Wb[640 * 128];              // packed big weight, fp16, [n][k]
__device__ __half g_Wih[384 * 128];             // W_ih fp16, [n][k]
__device__ float g_bias1[640];                  // [0,0,b_hh]
__device__ int   g_ccnt[CH * NN];
__device__ int   g_deg[NN];
__device__ int   g_off[NN + 1];
__device__ int   g_eid[EE];
__device__ int   g_esrc[EE];
__device__ float g_part[BB * 16 * DD];

__device__ __forceinline__ float selu_f(float x) {
    const float sc = 1.0507009873554805f, al = 1.6732632423543772f;
    return x > 0.f ? sc * x : sc * al * (__expf(x) - 1.f);
}

// ---------------- merged setup: weight pack + initial h convert ----------------
__global__ void k_prep(const float* __restrict__ Wmsg, const float* __restrict__ Whh,
                       const float* __restrict__ bhh, const float* __restrict__ Wih,
                       const float* __restrict__ nf) {
    int t = blockIdx.x * blockDim.x + threadIdx.x;
    if (t < 640 * 128) {
        int n = t >> 7, k = t & 127;
        float v;
        if (n < 128)       v = Wmsg[k * 128 + n];                 // src part
        else if (n < 256)  v = Wmsg[(128 + k) * 128 + (n - 128)]; // tgt part
        else               v = Whh[(n - 256) * 128 + k];          // W_hh^T
        g_Wb[t] = __float2half(v);
    }
    if (t < 384 * 128) g_Wih[t] = __float2half(Wih[t]);  // [384][128] == [n][k]
    if (t < 640) g_bias1[t] = (t < 256) ? 0.f : bhh[t - 256];
    if (t < BB * NN * DD) {
        float v = nf[t];
        __half hi = __float2half(v);
        g_hh[t] = hi;
        g_hl[t] = __float2half(v - __half2float(hi));
    }
}

// ---- CSR build: chunked histogram (deterministic stable order) ----
__global__ void k_cnt(const int* __restrict__ tgt) {  // grid CH, block 256
    __shared__ int c[NN];
    for (int i = threadIdx.x; i < NN; i += 256) c[i] = 0;
    __syncthreads();
    int e = blockIdx.x * CE + threadIdx.x;
    atomicAdd(&c[tgt[e]], 1);
    __syncthreads();
    for (int i = threadIdx.x; i < NN; i += 256) g_ccnt[blockIdx.x * NN + i] = c[i];
}

__global__ void k_tot() {  // grid 8, block 128
    int n = blockIdx.x * 128 + threadIdx.x;
    int s = 0;
#pragma unroll
    for (int c = 0; c < CH; ++c) s += g_ccnt[c * NN + n];
    g_deg[n] = s;
}

__global__ void k_scanx() {  // 1 block, 1024 threads: shfl 2-level scan
    __shared__ int wsum[32];
    int n = threadIdx.x, lane = n & 31, w = n >> 5;
    int v = g_deg[n];
    int sc = v;
#pragma unroll
    for (int o = 1; o < 32; o <<= 1) {
        int x = __shfl_up_sync(0xffffffffu, sc, o);
        if (lane >= o) sc += x;
    }
    if (lane == 31) wsum[w] = sc;
    __syncthreads();
    if (w == 0) {
        int s = wsum[lane];
#pragma unroll
        for (int o = 1; o < 32; o <<= 1) {
            int x = __shfl_up_sync(0xffffffffu, s, o);
            if (lane >= o) s += x;
        }
        wsum[lane] = s;
    }
    __syncthreads();
    int base = (w > 0) ? wsum[w - 1] : 0;
    g_off[n + 1] = base + sc;
    if (n == 0) g_off[0] = 0;
}

__global__ void k_offk() {  // grid 8, block 128
    int n = blockIdx.x * 128 + threadIdx.x;
    int run = g_off[n];
#pragma unroll
    for (int c = 0; c < CH; ++c) {
        int v = g_ccnt[c * NN + n];
        g_ccnt[c * NN + n] = run;
        run += v;
    }
}

__global__ void k_fill(const int* __restrict__ tgt, const int* __restrict__ src) {
    __shared__ int ctr[NN];
    int lane = threadIdx.x;
    int chunk = blockIdx.x;
    for (int i = lane; i < NN; i += 32) ctr[i] = g_ccnt[chunk * NN + i];
    __syncwarp();
    for (int r = 0; r < CE / 32; ++r) {
        int e = chunk * CE + r * 32 + lane;
        int t = tgt[e];
        unsigned mask = __match_any_sync(0xffffffffu, t);
        int leader = __ffs(mask) - 1;
        int rank = __popc(mask & ((1u << lane) - 1u));
        int base = 0;
        if (lane == leader) { base = ctr[t]; ctr[t] = base + __popc(mask); }
        base = __shfl_sync(0xffffffffu, base, leader);
        g_eid[base + rank] = e;
        g_esrc[base + rank] = src[e];
        __syncwarp();
    }
}

// gather edge scalars into CSR slot order (after k_fill)
__global__ void k_ef(const float* __restrict__ edge, const int* __restrict__ src,
                     const int* __restrict__ tgt) {
    int t = blockIdx.x * blockDim.x + threadIdx.x;
    if (t < BB * EE) {
        int b = t / EE, slot = t % EE;
        int e = g_eid[slot];
        g_ef[t] = edge[(size_t)b * NN * NN + (size_t)src[e] * NN + tgt[e]];
    }
}

// ---------------- persistent weight-stationary split-fp16 HMMA GEMM ----------------
// C = (Ah + Al) @ B + bias, A split fp16 (near-exact), B single fp16.
// 32-row A panels (warp tile 16x32), resident 128-col B panel, 3 CTAs/SM.
// MODE 0: gemm0 — cols 0..255 -> g_msg (fp16); cols 256..639 -> g_gh (fp16)
// MODE 1: gemm1 — fp16 store to Cg (stride 384)
#define SROW 136                          // padded row in fp16 elems
#define B_H 0
#define A_BASE (128 * SROW)               // two buffers of (32 hi + 32 lo) rows
#define MM_SMEM ((128 + 2 * 64) * SROW * 2)  // 69632 bytes -> 3 blocks/SM
#define MPAN 512                          // 16384 rows / 32

__device__ __forceinline__ void cp16(uint32_t dst, const void* src) {
    asm volatile("cp.async.cg.shared.global [%0], [%1], 16;" :: "r"(dst), "l"(src));
}
__device__ __forceinline__ void ldsm4(uint32_t& r0, uint32_t& r1, uint32_t& r2, uint32_t& r3,
                                      uint32_t addr) {
    asm volatile("ldmatrix.sync.aligned.m8n8.x4.shared.b16 {%0,%1,%2,%3},[%4];"
                 : "=r"(r0), "=r"(r1), "=r"(r2), "=r"(r3) : "r"(addr));
}
__device__ __forceinline__ void mma_f16(float* d, const uint32_t* a, const uint32_t* b) {
    asm volatile(
        "mma.sync.aligned.m16n8k16.row.col.f32.f16.f16.f32 "
        "{%0,%1,%2,%3},{%4,%5,%6,%7},{%8,%9},{%0,%1,%2,%3};"
        : "+f"(d[0]), "+f"(d[1]), "+f"(d[2]), "+f"(d[3])
        : "r"(a[0]), "r"(a[1]), "r"(a[2]), "r"(a[3]), "r"(b[0]), "r"(b[1]));
}

template <int MODE, int Nc>
__global__ __launch_bounds__(256, 3) void k_mm(const __half* __restrict__ Ahg,
                                               const __half* __restrict__ Alg,
                                               const __half* __restrict__ Bg,
                                               const float* __restrict__ bias,
                                               __half* __restrict__ Cm,
                                               __half* __restrict__ Cg) {
    extern __shared__ char smraw[];
    const int tid = threadIdx.x;
    const int bn = blockIdx.x;
    const int step = gridDim.y;
    const int lane = tid & 31, w = tid >> 5;
    const int wm = w >> 2, wn = w & 3;       // warp grid 2(m) x 4(n)

    uint32_t sbase = (uint32_t)__cvta_generic_to_shared(smraw);

    // ---- resident B panel: 128 cols x 128 k, fp16 single ----
    const __half* Bo = Bg + (size_t)(bn * 128) * 128;
#pragma unroll
    for (int i = 0; i < 8; ++i) {
        int idx = tid + i * 256;
        int row = idx >> 4, c8 = (idx & 15) * 8;
        uint32_t so = (uint32_t)(row * SROW + c8) * 2;
        cp16(sbase + B_H * 2 + so, Bo + (size_t)row * 128 + c8);
    }

    auto loadA = [&](int bm, int buf) {
        const __half* Aho = Ahg + (size_t)(bm * 32) * 128;
        const __half* Alo = Alg + (size_t)(bm * 32) * 128;
        uint32_t ab = sbase + (uint32_t)(A_BASE + buf * 64 * SROW) * 2;
#pragma unroll
        for (int i = 0; i < 2; ++i) {
            int idx = tid + i * 256;
            int row = idx >> 4, c8 = (idx & 15) * 8;
            uint32_t so = (uint32_t)(row * SROW + c8) * 2;
            size_t g = (size_t)row * 128 + c8;
            cp16(ab + so, Aho + g);
            cp16(ab + (uint32_t)(32 * SROW) * 2 + so, Alo + g);
        }
    };

    const int bm0 = blockIdx.y;
    loadA(bm0, 0);
    asm volatile("cp.async.commit_group;" ::: "memory");

    const int grp = lane >> 2, qp = lane & 3;
    float2 bv[4];
#pragma unroll
    for (int nt = 0; nt < 4; ++nt) {
        int col = bn * 128 + wn * 32 + nt * 8 + qp * 2;
        bv[nt] = *(const float2*)(bias + col);
    }

    const int arow = wm * 16 + (lane & 15);
    const int akof = (lane >> 4) << 3;
    const int bnrow = wn * 32 + ((lane >> 4) << 3) + (lane & 7);
    const int bkof = ((lane >> 3) & 1) << 3;

    int buf = 0;
    for (int bm = bm0; bm < MPAN; bm += step) {
        int nxt = bm + step;
        if (nxt < MPAN) {
            loadA(nxt, buf ^ 1);
            asm volatile("cp.async.commit_group;" ::: "memory");
            asm volatile("cp.async.wait_group 1;" ::: "memory");
        } else {
            asm volatile("cp.async.wait_group 0;" ::: "memory");
        }
        __syncthreads();

        uint32_t abase = sbase + (uint32_t)(A_BASE + buf * 64 * SROW) * 2;
        uint32_t lbase = abase + (uint32_t)(32 * SROW) * 2;

        float acc[4][4];
#pragma unroll
        for (int nt = 0; nt < 4; ++nt)
#pragma unroll
            for (int q = 0; q < 4; ++q) acc[nt][q] = 0.f;

        uint32_t ah[2][4], al[2][4], bh[2][2][4];
        auto ldfr = [&](int ks, int fb) {
            int k0 = ks * 16;
            uint32_t aoff = (uint32_t)(arow * SROW + k0 + akof) * 2;
            ldsm4(ah[fb][0], ah[fb][1], ah[fb][2], ah[fb][3], abase + aoff);
            ldsm4(al[fb][0], al[fb][1], al[fb][2], al[fb][3], lbase + aoff);
#pragma unroll
            for (int np = 0; np < 2; ++np) {
                uint32_t off = (uint32_t)((bnrow + np * 16) * SROW + k0 + bkof) * 2;
                ldsm4(bh[fb][np][0], bh[fb][np][1], bh[fb][np][2], bh[fb][np][3],
                      sbase + B_H * 2 + off);
            }
        };

        ldfr(0, 0);
#pragma unroll
        for (int ks = 0; ks < 8; ++ks) {
            int fb = ks & 1;
            if (ks < 7) ldfr(ks + 1, fb ^ 1);
#pragma unroll
            for (int nt = 0; nt < 4; ++nt) {
                const uint32_t* bhp = &bh[fb][nt >> 1][(nt & 1) * 2];
                mma_f16(acc[nt], ah[fb], bhp);
                mma_f16(acc[nt], al[fb], bhp);
            }
        }

        int row = bm * 32 + wm * 16 + grp;
        if (MODE == 1) {
            // gi -> fp16, row stride 384
#pragma unroll
            for (int nt = 0; nt < 4; ++nt) {
                int col = bn * 128 + wn * 32 + nt * 8 + qp * 2;
                __half2 v0 = __floats2half2_rn(acc[nt][0] + bv[nt].x, acc[nt][1] + bv[nt].y);
                __half2 v1 = __floats2half2_rn(acc[nt][2] + bv[nt].x, acc[nt][3] + bv[nt].y);
                *(__half2*)(Cg + (size_t)row * 384 + col) = v0;
                *(__half2*)(Cg + (size_t)(row + 8) * 384 + col) = v1;
            }
        } else if (bn < 2) {
            // message part -> fp16, row stride 256
#pragma unroll
            for (int nt = 0; nt < 4; ++nt) {
                int col = bn * 128 + wn * 32 + nt * 8 + qp * 2;
                __half2 v0 = __floats2half2_rn(acc[nt][0] + bv[nt].x, acc[nt][1] + bv[nt].y);
                __half2 v1 = __floats2half2_rn(acc[nt][2] + bv[nt].x, acc[nt][3] + bv[nt].y);
                *(__half2*)(Cm + (size_t)row * 256 + col) = v0;
                *(__half2*)(Cm + (size_t)(row + 8) * 256 + col) = v1;
            }
        } else {
            // gh part -> fp16, row stride 384
#pragma unroll
            for (int nt = 0; nt < 4; ++nt) {
                int col = bn * 128 + wn * 32 + nt * 8 + qp * 2 - 256;
                __half2 v0 = __floats2half2_rn(acc[nt][0] + bv[nt].x, acc[nt][1] + bv[nt].y);
                __half2 v1 = __floats2half2_rn(acc[nt][2] + bv[nt].x, acc[nt][3] + bv[nt].y);
                *(__half2*)(Cg + (size_t)row * 384 + col) = v0;
                *(__half2*)(Cg + (size_t)(row + 8) * 384 + col) = v1;
            }
        }
        __syncthreads();
        buf ^= 1;
    }
}

// ---------------- fused edge message + deterministic aggregation (fp16 gathers) ----------------
__device__ __forceinline__ float4 h4tof4(uint2 u) {
    __half2 a = *(__half2*)&u.x, b = *(__half2*)&u.y;
    float2 fa = __half22float2(a), fb = __half22float2(b);
    return make_float4(fa.x, fa.y, fb.x, fb.y);
}

__global__ __launch_bounds__(256) void k_edge(const float* __restrict__ Wmsg,
                                              const float* __restrict__ bmsg) {
    int lane = threadIdx.x & 31;
    int nl = threadIdx.x >> 5;            // 8 nodes per block
    int n = blockIdx.x * 8 + nl;
    int b = blockIdx.y;
    float4 we = *(const float4*)(Wmsg + 256 * 128 + lane * 4);
    float4 bm = *(const float4*)(bmsg + lane * 4);
    const __half* msgb = g_msg + (size_t)b * NN * 256;
    float4 ht = h4tof4(*(const uint2*)(msgb + (size_t)n * 256 + 128 + lane * 4));
    float4 base = {ht.x + bm.x, ht.y + bm.y, ht.z + bm.z, ht.w + bm.w};
    const float* efb = g_ef + (size_t)b * EE;
    int s0 = g_off[n], s1 = g_off[n + 1];
    float4 acc = {0.f, 0.f, 0.f, 0.f};
    int s = s0;
    for (; s + 4 <= s1; s += 4) {
        int sr0 = g_esrc[s], sr1 = g_esrc[s + 1], sr2 = g_esrc[s + 2], sr3 = g_esrc[s + 3];
        float e0 = efb[s], e1 = efb[s + 1], e2 = efb[s + 2], e3 = efb[s + 3];
        float4 h0 = h4tof4(*(const uint2*)(msgb + (size_t)sr0 * 256 + lane * 4));
        float4 h1 = h4tof4(*(const uint2*)(msgb + (size_t)sr1 * 256 + lane * 4));
        float4 h2 = h4tof4(*(const uint2*)(msgb + (size_t)sr2 * 256 + lane * 4));
        float4 h3 = h4tof4(*(const uint2*)(msgb + (size_t)sr3 * 256 + lane * 4));
        acc.x += selu_f(h0.x + base.x + e0 * we.x) + selu_f(h1.x + base.x + e1 * we.x)
               + selu_f(h2.x + base.x + e2 * we.x) + selu_f(h3.x + base.x + e3 * we.x);
        acc.y += selu_f(h0.y + base.y + e0 * we.y) + selu_f(h1.y + base.y + e1 * we.y)
               + selu_f(h2.y + base.y + e2 * we.y) + selu_f(h3.y + base.y + e3 * we.y);
        acc.z += selu_f(h0.z + base.z + e0 * we.z) + selu_f(h1.z + base.z + e1 * we.z)
               + selu_f(h2.z + base.z + e2 * we.z) + selu_f(h3.z + base.z + e3 * we.z);
        acc.w += selu_f(h0.w + base.w + e0 * we.w) + selu_f(h1.w + base.w + e1 * we.w)
               + selu_f(h2.w + base.w + e2 * we.w) + selu_f(h3.w + base.w + e3 * we.w);
    }
    for (; s < s1; ++s) {
        int sr0 = g_esrc[s];
        float e0 = efb[s];
        float4 h0 = h4tof4(*(const uint2*)(msgb + (size_t)sr0 * 256 + lane * 4));
        acc.x += selu_f(h0.x + base.x + e0 * we.x);
        acc.y += selu_f(h0.y + base.y + e0 * we.y);
        acc.z += selu_f(h0.z + base.z + e0 * we.z);
        acc.w += selu_f(h0.w + base.w + e0 * we.w);
    }
    size_t o = ((size_t)(b * NN + n)) * DD + lane * 4;
    float a4[4] = {acc.x, acc.y, acc.z, acc.w};
    __half hi4[4], lo4[4];
#pragma unroll
    for (int j = 0; j < 4; ++j) {
        hi4[j] = __float2half(a4[j]);
        lo4[j] = __float2half(a4[j] - __half2float(hi4[j]));
    }
    *(uint2*)(g_aggh + o) = *(uint2*)hi4;
    *(uint2*)(g_aggl + o) = *(uint2*)lo4;
}

// ---------------- GRU elementwise, fp16 gi/gh ----------------
__global__ void k_gru(const float* __restrict__ hprev) {
    int t = blockIdx.x * blockDim.x + threadIdx.x;   // BB*NN*32 threads
    if (t >= BB * NN * 32) return;
    int row = t >> 5, q = t & 31;
    const __half* gi = g_gi + (size_t)row * 384 + q * 4;
    const __half* gh = g_gh + (size_t)row * 384 + q * 4;
    float4 ir4 = h4tof4(*(const uint2*)gi);
    float4 iz4 = h4tof4(*(const uint2*)(gi + 128));
    float4 in4 = h4tof4(*(const uint2*)(gi + 256));
    float4 hr4 = h4tof4(*(const uint2*)gh);
    float4 hz4 = h4tof4(*(const uint2*)(gh + 128));
    float4 hn4 = h4tof4(*(const uint2*)(gh + 256));
    float4 h4 = *(const float4*)(hprev + (size_t)row * 128 + q * 4);
    float* irp = (float*)&ir4; float* izp = (float*)&iz4; float* inp = (float*)&in4;
    float* hrp = (float*)&hr4; float* hzp = (float*)&hz4; float* hnp = (float*)&hn4;
    float* hp = (float*)&h4;
    float4 o4;
    float* op = (float*)&o4;
    __half hi4[4], lo4[4];
#pragma unroll
    for (int j = 0; j < 4; ++j) {
        float r = 1.f / (1.f + __expf(-(irp[j] + hrp[j])));
        float z = 1.f / (1.f + __expf(-(izp[j] + hzp[j])));
        float nv = tanhf(inp[j] + r * hnp[j]);
        float hn2 = (1.f - z) * nv + z * hp[j];
        op[j] = hn2;
        hi4[j] = __float2half(hn2);
        lo4[j] = __float2half(hn2 - __half2float(hi4[j]));
    }
    size_t o = (size_t)row * 128 + q * 4;
    *(float4*)(g_h + o) = o4;
    *(uint2*)(g_hh + o) = *(uint2*)hi4;
    *(uint2*)(g_hl + o) = *(uint2*)lo4;
}

// ---------------- pooling + readout head ----------------
__global__ void k_pool() {
    int c = blockIdx.x, b = blockIdx.y, d = threadIdx.x;
    const float* hb = g_h + ((size_t)b * NN + c * 64) * DD + d;
    float s = 0.f;
#pragma unroll 8
    for (int n = 0; n < 64; ++n) s += hb[(size_t)n * DD];
    g_part[(b * 16 + c) * DD + d] = s;
}

__global__ void k_head(const float* __restrict__ Wr1, const float* __restrict__ br1,
                       const float* __restrict__ Wr2, const float* __restrict__ br2,
                       const float* __restrict__ Wpol, const float* __restrict__ bpol,
                       float* __restrict__ out) {
    int b = blockIdx.x, d = threadIdx.x;
    __shared__ float p[128], q[128];
    float s = 0.f;
#pragma unroll
    for (int c = 0; c < 16; ++c) s += g_part[(b * 16 + c) * DD + d];
    p[d] = s;
    __syncthreads();
    float y = br1[d];
#pragma unroll 8
    for (int k = 0; k < 128; ++k) y = fmaf(p[k], Wr1[k * 128 + d], y);
    q[d] = selu_f(y);
    __syncthreads();
    y = br2[d];
#pragma unroll 8
    for (int k = 0; k < 128; ++k) y = fmaf(q[k], Wr2[k * 128 + d], y);
    float p2 = selu_f(y);
    __syncthreads();
    p[d] = p2;
    __syncthreads();
    if (d < 64) {
        float o = bpol[d];
#pragma unroll 8
        for (int k = 0; k < 128; ++k) o = fmaf(p[k], Wpol[k * 64 + d], o);
        out[b * 64 + d] = o;
    }
}

// ---------------- launch ----------------
extern "C" void kernel_launch(void* const* d_in, const int* in_sizes, int n_in,
                              void* d_out, int out_size) {
    const float* nf   = (const float*)d_in[0];
    const float* edge = (const float*)d_in[1];
    const int*   src  = (const int*)d_in[2];
    const int*   tgt  = (const int*)d_in[3];
    const float* Wmsg = (const float*)d_in[4];
    const float* bmsg = (const float*)d_in[5];
    const float* Wih  = (const float*)d_in[6];
    const float* Whh  = (const float*)d_in[7];
    const float* bih  = (const float*)d_in[8];
    const float* bhh  = (const float*)d_in[9];
    const float* Wr1  = (const float*)d_in[10];
    const float* br1  = (const float*)d_in[11];
    const float* Wr2  = (const float*)d_in[12];
    const float* br2  = (const float*)d_in[13];
    const float* Wpol = (const float*)d_in[14];
    const float* bpol = (const float*)d_in[15];
    float* out = (float*)d_out;

    float *g_h_p, *g_bias1_p;
    __half *gh_p, *gi_p, *msg_p, *wb_p, *wih_p, *hh_p, *hl_p, *aggh_p, *aggl_p;
    cudaGetSymbolAddress((void**)&g_h_p, g_h);
    cudaGetSymbolAddress((void**)&gh_p, g_gh);
    cudaGetSymbolAddress((void**)&gi_p, g_gi);
    cudaGetSymbolAddress((void**)&g_bias1_p, g_bias1);
    cudaGetSymbolAddress((void**)&msg_p, g_msg);
    cudaGetSymbolAddress((void**)&wb_p, g_Wb);
    cudaGetSymbolAddress((void**)&wih_p, g_Wih);
    cudaGetSymbolAddress((void**)&hh_p, g_hh);
    cudaGetSymbolAddress((void**)&hl_p, g_hl);
    cudaGetSymbolAddress((void**)&aggh_p, g_aggh);
    cudaGetSymbolAddress((void**)&aggl_p, g_aggl);

    cudaFuncSetAttribute((const void*)k_mm<0, 640>,
                         cudaFuncAttributeMaxDynamicSharedMemorySize, MM_SMEM);
    cudaFuncSetAttribute((const void*)k_mm<1, 384>,
                         cudaFuncAttributeMaxDynamicSharedMemorySize, MM_SMEM);

    // launch index 3 == first k_mm<0,640> (profiled)
    k_prep<<<(BB * NN * DD + 255) / 256, 256>>>(Wmsg, Whh, bhh, Wih, nf);
    k_cnt<<<CH, 256>>>(tgt);
    k_tot<<<8, 128>>>();
    k_mm<0, 640><<<dim3(5, 88), 256, MM_SMEM>>>(hh_p, hl_p, wb_p, g_bias1_p,
                                                msg_p, gh_p);
    k_scanx<<<1, NN>>>();
    k_offk<<<8, 128>>>();
    k_fill<<<CH, 32>>>(tgt, src);
    k_ef<<<(BB * EE + 255) / 256, 256>>>(edge, src, tgt);

    for (int it = 0; it < DIAM; ++it) {
        if (it > 0)
            k_mm<0, 640><<<dim3(5, 88), 256, MM_SMEM>>>(hh_p, hl_p, wb_p, g_bias1_p,
                                                        msg_p, gh_p);
        k_edge<<<dim3(NN / 8, BB), 256>>>(Wmsg, bmsg);
        k_mm<1, 384><<<dim3(3, 148), 256, MM_SMEM>>>(aggh_p, aggl_p, wih_p, bih,
                                                     nullptr, gi_p);
        k_gru<<<(BB * NN * 32 + 255) / 256, 256>>>(it == 0 ? nf : g_h_p);
    }

    k_pool<<<dim3(16, BB), 128>>>();
    k_head<<<BB, 128>>>(Wr1, br1, Wr2, br2, Wpol, bpol, out);
}

// round 17
// speedup vs baseline: 1.1164x; 1.0488x over previous
#include <cuda_runtime.h>
#include <cuda_bf16.h>
#include <cuda_fp16.h>
#include <cstdint>

// Problem constants
#define BB   16
#define NN   1024
#define DD   128
#define EE   16384
#define AA   64
#define DIAM 3
#define CH   64           // edge chunks for CSR build
#define CE   (EE / CH)    // 256 edges per chunk

// ---------------- device scratch (no allocations allowed) ----------------
__device__ float g_h[BB * NN * DD];             // node state fp32
__device__ __half g_hh[BB * NN * DD];           // h hi (fp16)
__device__ __half g_hl[BB * NN * DD];           // h lo (fp16 residual)
__device__ __half g_msg[BB * NN * 256];         // [hs|ht] per node, fp16
__device__ __half g_gh[BB * NN * 384];          // gh per node, fp16
__device__ __half g_agg[BB * NN * DD];          // agg, fp16 single
__device__ __half g_gi[BB * NN * 384];          // gi = agg@Wih^T, fp16
__device__ float g_ef[BB * EE];                 // edge scalars, CSR slot order
__device__ __half g_Wb[640 * 128];              // packed big weight, fp16, [n][k]
__device__ __half g_Wih[384 * 128];             // W_ih fp16, [n][k]
__device__ float g_bias1[640];                  // [0,0,b_hh]
__device__ int   g_ccnt[CH * NN];
__device__ int   g_deg[NN];
__device__ int   g_off[NN + 1];
__device__ int   g_eid[EE];
__device__ int   g_esrc[EE];
__device__ float g_part[BB * 16 * DD];

__device__ __forceinline__ float selu_f(float x) {
    const float sc = 1.0507009873554805f, al = 1.6732632423543772f;
    return x > 0.f ? sc * x : sc * al * (__expf(x) - 1.f);
}

// ---------------- merged setup: weight pack + initial h convert ----------------
__global__ void k_prep(const float* __restrict__ Wmsg, const float* __restrict__ Whh,
                       const float* __restrict__ bhh, const float* __restrict__ Wih,
                       const float* __restrict__ nf) {
    int t = blockIdx.x * blockDim.x + threadIdx.x;
    if (t < 640 * 128) {
        int n = t >> 7, k = t & 127;
        float v;
        if (n < 128)       v = Wmsg[k * 128 + n];                 // src part
        else if (n < 256)  v = Wmsg[(128 + k) * 128 + (n - 128)]; // tgt part
        else               v = Whh[(n - 256) * 128 + k];          // W_hh^T
        g_Wb[t] = __float2half(v);
    }
    if (t < 384 * 128) g_Wih[t] = __float2half(Wih[t]);  // [384][128] == [n][k]
    if (t < 640) g_bias1[t] = (t < 256) ? 0.f : bhh[t - 256];
    if (t < BB * NN * DD) {
        float v = nf[t];
        __half hi = __float2half(v);
        g_hh[t] = hi;
        g_hl[t] = __float2half(v - __half2float(hi));
    }
}

// ---- CSR build: chunked histogram (deterministic stable order) ----
__global__ void k_cnt(const int* __restrict__ tgt) {  // grid CH, block 256
    __shared__ int c[NN];
    for (int i = threadIdx.x; i < NN; i += 256) c[i] = 0;
    __syncthreads();
    int e = blockIdx.x * CE + threadIdx.x;
    atomicAdd(&c[tgt[e]], 1);
    __syncthreads();
    for (int i = threadIdx.x; i < NN; i += 256) g_ccnt[blockIdx.x * NN + i] = c[i];
}

__global__ void k_tot() {  // grid 8, block 128
    int n = blockIdx.x * 128 + threadIdx.x;
    int s = 0;
#pragma unroll
    for (int c = 0; c < CH; ++c) s += g_ccnt[c * NN + n];
    g_deg[n] = s;
}

__global__ void k_scanx() {  // 1 block, 1024 threads: shfl 2-level scan
    __shared__ int wsum[32];
    int n = threadIdx.x, lane = n & 31, w = n >> 5;
    int v = g_deg[n];
    int sc = v;
#pragma unroll
    for (int o = 1; o < 32; o <<= 1) {
        int x = __shfl_up_sync(0xffffffffu, sc, o);
        if (lane >= o) sc += x;
    }
    if (lane == 31) wsum[w] = sc;
    __syncthreads();
    if (w == 0) {
        int s = wsum[lane];
#pragma unroll
        for (int o = 1; o < 32; o <<= 1) {
            int x = __shfl_up_sync(0xffffffffu, s, o);
            if (lane >= o) s += x;
        }
        wsum[lane] = s;
    }
    __syncthreads();
    int base = (w > 0) ? wsum[w - 1] : 0;
    g_off[n + 1] = base + sc;
    if (n == 0) g_off[0] = 0;
}

__global__ void k_offk() {  // grid 8, block 128
    int n = blockIdx.x * 128 + threadIdx.x;
    int run = g_off[n];
#pragma unroll
    for (int c = 0; c < CH; ++c) {
        int v = g_ccnt[c * NN + n];
        g_ccnt[c * NN + n] = run;
        run += v;
    }
}

__global__ void k_fill(const int* __restrict__ tgt, const int* __restrict__ src) {
    __shared__ int ctr[NN];
    int lane = threadIdx.x;
    int chunk = blockIdx.x;
    for (int i = lane; i < NN; i += 32) ctr[i] = g_ccnt[chunk * NN + i];
    __syncwarp();
    for (int r = 0; r < CE / 32; ++r) {
        int e = chunk * CE + r * 32 + lane;
        int t = tgt[e];
        unsigned mask = __match_any_sync(0xffffffffu, t);
        int leader = __ffs(mask) - 1;
        int rank = __popc(mask & ((1u << lane) - 1u));
        int base = 0;
        if (lane == leader) { base = ctr[t]; ctr[t] = base + __popc(mask); }
        base = __shfl_sync(0xffffffffu, base, leader);
        g_eid[base + rank] = e;
        g_esrc[base + rank] = src[e];
        __syncwarp();
    }
}

// gather edge scalars into CSR slot order (after k_fill)
__global__ void k_ef(const float* __restrict__ edge, const int* __restrict__ src,
                     const int* __restrict__ tgt) {
    int t = blockIdx.x * blockDim.x + threadIdx.x;
    if (t < BB * EE) {
        int b = t / EE, slot = t % EE;
        int e = g_eid[slot];
        g_ef[t] = edge[(size_t)b * NN * NN + (size_t)src[e] * NN + tgt[e]];
    }
}

// ---------------- persistent weight-stationary fp16 HMMA GEMM ----------------
// SPLIT=1: C = (Ah + Al) @ B + bias (A split fp16, near-exact)
// SPLIT=0: C = Ah @ B + bias (A single fp16)
// 32-row A panels (warp tile 16x32), resident 128-col B panel, 3 CTAs/SM.
// MODE 0: gemm0 — cols 0..255 -> g_msg (fp16); cols 256..639 -> g_gh (fp16)
// MODE 1: gemm1 — fp16 store to Cg (stride 384)
#define SROW 136                          // padded row in fp16 elems
#define B_H 0
#define A_BASE (128 * SROW)               // two buffers of (32 hi + 32 lo) rows
#define MM_SMEM ((128 + 2 * 64) * SROW * 2)  // 69632 bytes -> 3 blocks/SM
#define MPAN 512                          // 16384 rows / 32

__device__ __forceinline__ void cp16(uint32_t dst, const void* src) {
    asm volatile("cp.async.cg.shared.global [%0], [%1], 16;" :: "r"(dst), "l"(src));
}
__device__ __forceinline__ void ldsm4(uint32_t& r0, uint32_t& r1, uint32_t& r2, uint32_t& r3,
                                      uint32_t addr) {
    asm volatile("ldmatrix.sync.aligned.m8n8.x4.shared.b16 {%0,%1,%2,%3},[%4];"
                 : "=r"(r0), "=r"(r1), "=r"(r2), "=r"(r3) : "r"(addr));
}
__device__ __forceinline__ void mma_f16(float* d, const uint32_t* a, const uint32_t* b) {
    asm volatile(
        "mma.sync.aligned.m16n8k16.row.col.f32.f16.f16.f32 "
        "{%0,%1,%2,%3},{%4,%5,%6,%7},{%8,%9},{%0,%1,%2,%3};"
        : "+f"(d[0]), "+f"(d[1]), "+f"(d[2]), "+f"(d[3])
        : "r"(a[0]), "r"(a[1]), "r"(a[2]), "r"(a[3]), "r"(b[0]), "r"(b[1]));
}

template <int MODE, int Nc, int SPLIT>
__global__ __launch_bounds__(256, 3) void k_mm(const __half* __restrict__ Ahg,
                                               const __half* __restrict__ Alg,
                                               const __half* __restrict__ Bg,
                                               const float* __restrict__ bias,
                                               __half* __restrict__ Cm,
                                               __half* __restrict__ Cg) {
    extern __shared__ char smraw[];
    const int tid = threadIdx.x;
    const int bn = blockIdx.x;
    const int step = gridDim.y;
    const int lane = tid & 31, w = tid >> 5;
    const int wm = w >> 2, wn = w & 3;       // warp grid 2(m) x 4(n)

    uint32_t sbase = (uint32_t)__cvta_generic_to_shared(smraw);

    // ---- resident B panel: 128 cols x 128 k, fp16 single ----
    const __half* Bo = Bg + (size_t)(bn * 128) * 128;
#pragma unroll
    for (int i = 0; i < 8; ++i) {
        int idx = tid + i * 256;
        int row = idx >> 4, c8 = (idx & 15) * 8;
        uint32_t so = (uint32_t)(row * SROW + c8) * 2;
        cp16(sbase + B_H * 2 + so, Bo + (size_t)row * 128 + c8);
    }

    auto loadA = [&](int bm, int buf) {
        const __half* Aho = Ahg + (size_t)(bm * 32) * 128;
        const __half* Alo = Alg + (size_t)(bm * 32) * 128;
        uint32_t ab = sbase + (uint32_t)(A_BASE + buf * 64 * SROW) * 2;
#pragma unroll
        for (int i = 0; i < 2; ++i) {
            int idx = tid + i * 256;
            int row = idx >> 4, c8 = (idx & 15) * 8;
            uint32_t so = (uint32_t)(row * SROW + c8) * 2;
            size_t g = (size_t)row * 128 + c8;
            cp16(ab + so, Aho + g);
            if (SPLIT) cp16(ab + (uint32_t)(32 * SROW) * 2 + so, Alo + g);
        }
    };

    const int bm0 = blockIdx.y;
    loadA(bm0, 0);
    asm volatile("cp.async.commit_group;" ::: "memory");

    const int grp = lane >> 2, qp = lane & 3;
    float2 bv[4];
#pragma unroll
    for (int nt = 0; nt < 4; ++nt) {
        int col = bn * 128 + wn * 32 + nt * 8 + qp * 2;
        bv[nt] = *(const float2*)(bias + col);
    }

    const int arow = wm * 16 + (lane & 15);
    const int akof = (lane >> 4) << 3;
    const int bnrow = wn * 32 + ((lane >> 4) << 3) + (lane & 7);
    const int bkof = ((lane >> 3) & 1) << 3;

    int buf = 0;
    for (int bm = bm0; bm < MPAN; bm += step) {
        int nxt = bm + step;
        if (nxt < MPAN) {
            loadA(nxt, buf ^ 1);
            asm volatile("cp.async.commit_group;" ::: "memory");
            asm volatile("cp.async.wait_group 1;" ::: "memory");
        } else {
            asm volatile("cp.async.wait_group 0;" ::: "memory");
        }
        __syncthreads();

        uint32_t abase = sbase + (uint32_t)(A_BASE + buf * 64 * SROW) * 2;
        uint32_t lbase = abase + (uint32_t)(32 * SROW) * 2;

        float acc[4][4];
#pragma unroll
        for (int nt = 0; nt < 4; ++nt)
#pragma unroll
            for (int q = 0; q < 4; ++q) acc[nt][q] = 0.f;

        uint32_t ah[2][4], al[2][4], bh[2][2][4];
        auto ldfr = [&](int ks, int fb) {
            int k0 = ks * 16;
            uint32_t aoff = (uint32_t)(arow * SROW + k0 + akof) * 2;
            ldsm4(ah[fb][0], ah[fb][1], ah[fb][2], ah[fb][3], abase + aoff);
            if (SPLIT)
                ldsm4(al[fb][0], al[fb][1], al[fb][2], al[fb][3], lbase + aoff);
#pragma unroll
            for (int np = 0; np < 2; ++np) {
                uint32_t off = (uint32_t)((bnrow + np * 16) * SROW + k0 + bkof) * 2;
                ldsm4(bh[fb][np][0], bh[fb][np][1], bh[fb][np][2], bh[fb][np][3],
                      sbase + B_H * 2 + off);
            }
        };

        ldfr(0, 0);
#pragma unroll
        for (int ks = 0; ks < 8; ++ks) {
            int fb = ks & 1;
            if (ks < 7) ldfr(ks + 1, fb ^ 1);
#pragma unroll
            for (int nt = 0; nt < 4; ++nt) {
                const uint32_t* bhp = &bh[fb][nt >> 1][(nt & 1) * 2];
                mma_f16(acc[nt], ah[fb], bhp);
                if (SPLIT) mma_f16(acc[nt], al[fb], bhp);
            }
        }

        int row = bm * 32 + wm * 16 + grp;
        if (MODE == 1) {
            // gi -> fp16, row stride 384
#pragma unroll
            for (int nt = 0; nt < 4; ++nt) {
                int col = bn * 128 + wn * 32 + nt * 8 + qp * 2;
                __half2 v0 = __floats2half2_rn(acc[nt][0] + bv[nt].x, acc[nt][1] + bv[nt].y);
                __half2 v1 = __floats2half2_rn(acc[nt][2] + bv[nt].x, acc[nt][3] + bv[nt].y);
                *(__half2*)(Cg + (size_t)row * 384 + col) = v0;
                *(__half2*)(Cg + (size_t)(row + 8) * 384 + col) = v1;
            }
        } else if (bn < 2) {
            // message part -> fp16, row stride 256
#pragma unroll
            for (int nt = 0; nt < 4; ++nt) {
                int col = bn * 128 + wn * 32 + nt * 8 + qp * 2;
                __half2 v0 = __floats2half2_rn(acc[nt][0] + bv[nt].x, acc[nt][1] + bv[nt].y);
                __half2 v1 = __floats2half2_rn(acc[nt][2] + bv[nt].x, acc[nt][3] + bv[nt].y);
                *(__half2*)(Cm + (size_t)row * 256 + col) = v0;
                *(__half2*)(Cm + (size_t)(row + 8) * 256 + col) = v1;
            }
        } else {
            // gh part -> fp16, row stride 384
#pragma unroll
            for (int nt = 0; nt < 4; ++nt) {
                int col = bn * 128 + wn * 32 + nt * 8 + qp * 2 - 256;
                __half2 v0 = __floats2half2_rn(acc[nt][0] + bv[nt].x, acc[nt][1] + bv[nt].y);
                __half2 v1 = __floats2half2_rn(acc[nt][2] + bv[nt].x, acc[nt][3] + bv[nt].y);
                *(__half2*)(Cg + (size_t)row * 384 + col) = v0;
                *(__half2*)(Cg + (size_t)(row + 8) * 384 + col) = v1;
            }
        }
        __syncthreads();
        buf ^= 1;
    }
}

// ---------------- fused edge message + deterministic aggregation (fp16 gathers) ----------------
__device__ __forceinline__ float4 h4tof4(uint2 u) {
    __half2 a = *(__half2*)&u.x, b = *(__half2*)&u.y;
    float2 fa = __half22float2(a), fb = __half22float2(b);
    return make_float4(fa.x, fa.y, fb.x, fb.y);
}

__global__ __launch_bounds__(256) void k_edge(const float* __restrict__ Wmsg,
                                              const float* __restrict__ bmsg) {
    int lane = threadIdx.x & 31;
    int nl = threadIdx.x >> 5;            // 8 nodes per block
    int n = blockIdx.x * 8 + nl;
    int b = blockIdx.y;
    float4 we = *(const float4*)(Wmsg + 256 * 128 + lane * 4);
    float4 bm = *(const float4*)(bmsg + lane * 4);
    const __half* msgb = g_msg + (size_t)b * NN * 256;
    float4 ht = h4tof4(*(const uint2*)(msgb + (size_t)n * 256 + 128 + lane * 4));
    float4 base = {ht.x + bm.x, ht.y + bm.y, ht.z + bm.z, ht.w + bm.w};
    const float* efb = g_ef + (size_t)b * EE;
    int s0 = g_off[n], s1 = g_off[n + 1];
    float4 acc = {0.f, 0.f, 0.f, 0.f};
    int s = s0;
    for (; s + 4 <= s1; s += 4) {
        int sr0 = g_esrc[s], sr1 = g_esrc[s + 1], sr2 = g_esrc[s + 2], sr3 = g_esrc[s + 3];
        float e0 = efb[s], e1 = efb[s + 1], e2 = efb[s + 2], e3 = efb[s + 3];
        float4 h0 = h4tof4(*(const uint2*)(msgb + (size_t)sr0 * 256 + lane * 4));
        float4 h1 = h4tof4(*(const uint2*)(msgb + (size_t)sr1 * 256 + lane * 4));
        float4 h2 = h4tof4(*(const uint2*)(msgb + (size_t)sr2 * 256 + lane * 4));
        float4 h3 = h4tof4(*(const uint2*)(msgb + (size_t)sr3 * 256 + lane * 4));
        acc.x += selu_f(h0.x + base.x + e0 * we.x) + selu_f(h1.x + base.x + e1 * we.x)
               + selu_f(h2.x + base.x + e2 * we.x) + selu_f(h3.x + base.x + e3 * we.x);
        acc.y += selu_f(h0.y + base.y + e0 * we.y) + selu_f(h1.y + base.y + e1 * we.y)
               + selu_f(h2.y + base.y + e2 * we.y) + selu_f(h3.y + base.y + e3 * we.y);
        acc.z += selu_f(h0.z + base.z + e0 * we.z) + selu_f(h1.z + base.z + e1 * we.z)
               + selu_f(h2.z + base.z + e2 * we.z) + selu_f(h3.z + base.z + e3 * we.z);
        acc.w += selu_f(h0.w + base.w + e0 * we.w) + selu_f(h1.w + base.w + e1 * we.w)
               + selu_f(h2.w + base.w + e2 * we.w) + selu_f(h3.w + base.w + e3 * we.w);
    }
    for (; s < s1; ++s) {
        int sr0 = g_esrc[s];
        float e0 = efb[s];
        float4 h0 = h4tof4(*(const uint2*)(msgb + (size_t)sr0 * 256 + lane * 4));
        acc.x += selu_f(h0.x + base.x + e0 * we.x);
        acc.y += selu_f(h0.y + base.y + e0 * we.y);
        acc.z += selu_f(h0.z + base.z + e0 * we.z);
        acc.w += selu_f(h0.w + base.w + e0 * we.w);
    }
    size_t o = ((size_t)(b * NN + n)) * DD + lane * 4;
    float a4[4] = {acc.x, acc.y, acc.z, acc.w};
    __half hi4[4];
#pragma unroll
    for (int j = 0; j < 4; ++j) hi4[j] = __float2half(a4[j]);
    *(uint2*)(g_agg + o) = *(uint2*)hi4;
}

// ---------------- GRU elementwise, fp16 gi/gh ----------------
__global__ void k_gru(const float* __restrict__ hprev) {
    int t = blockIdx.x * blockDim.x + threadIdx.x;   // BB*NN*32 threads
    if (t >= BB * NN * 32) return;
    int row = t >> 5, q = t & 31;
    const __half* gi = g_gi + (size_t)row * 384 + q * 4;
    const __half* gh = g_gh + (size_t)row * 384 + q * 4;
    float4 ir4 = h4tof4(*(const uint2*)gi);
    float4 iz4 = h4tof4(*(const uint2*)(gi + 128));
    float4 in4 = h4tof4(*(const uint2*)(gi + 256));
    float4 hr4 = h4tof4(*(const uint2*)gh);
    float4 hz4 = h4tof4(*(const uint2*)(gh + 128));
    float4 hn4 = h4tof4(*(const uint2*)(gh + 256));
    float4 h4 = *(const float4*)(hprev + (size_t)row * 128 + q * 4);
    float* irp = (float*)&ir4; float* izp = (float*)&iz4; float* inp = (float*)&in4;
    float* hrp = (float*)&hr4; float* hzp = (float*)&hz4; float* hnp = (float*)&hn4;
    float* hp = (float*)&h4;
    float4 o4;
    float* op = (float*)&o4;
    __half hi4[4], lo4[4];
#pragma unroll
    for (int j = 0; j < 4; ++j) {
        float r = 1.f / (1.f + __expf(-(irp[j] + hrp[j])));
        float z = 1.f / (1.f + __expf(-(izp[j] + hzp[j])));
        float nv = tanhf(inp[j] + r * hnp[j]);
        float hn2 = (1.f - z) * nv + z * hp[j];
        op[j] = hn2;
        hi4[j] = __float2half(hn2);
        lo4[j] = __float2half(hn2 - __half2float(hi4[j]));
    }
    size_t o = (size_t)row * 128 + q * 4;
    *(float4*)(g_h + o) = o4;
    *(uint2*)(g_hh + o) = *(uint2*)hi4;
    *(uint2*)(g_hl + o) = *(uint2*)lo4;
}

// ---------------- pooling + readout head ----------------
__global__ void k_pool() {
    int c = blockIdx.x, b = blockIdx.y, d = threadIdx.x;
    const float* hb = g_h + ((size_t)b * NN + c * 64) * DD + d;
    float s = 0.f;
#pragma unroll 8
    for (int n = 0; n < 64; ++n) s += hb[(size_t)n * DD];
    g_part[(b * 16 + c) * DD + d] = s;
}

__global__ void k_head(const float* __restrict__ Wr1, const float* __restrict__ br1,
                       const float* __restrict__ Wr2, const float* __restrict__ br2,
                       const float* __restrict__ Wpol, const float* __restrict__ bpol,
                       float* __restrict__ out) {
    int b = blockIdx.x, d = threadIdx.x;
    __shared__ float p[128], q[128];
    float s = 0.f;
#pragma unroll
    for (int c = 0; c < 16; ++c) s += g_part[(b * 16 + c) * DD + d];
    p[d] = s;
    __syncthreads();
    float y = br1[d];
#pragma unroll 8
    for (int k = 0; k < 128; ++k) y = fmaf(p[k], Wr1[k * 128 + d], y);
    q[d] = selu_f(y);
    __syncthreads();
    y = br2[d];
#pragma unroll 8
    for (int k = 0; k < 128; ++k) y = fmaf(q[k], Wr2[k * 128 + d], y);
    float p2 = selu_f(y);
    __syncthreads();
    p[d] = p2;
    __syncthreads();
    if (d < 64) {
        float o = bpol[d];
#pragma unroll 8
        for (int k = 0; k < 128; ++k) o = fmaf(p[k], Wpol[k * 64 + d], o);
        out[b * 64 + d] = o;
    }
}

// ---------------- launch ----------------
extern "C" void kernel_launch(void* const* d_in, const int* in_sizes, int n_in,
                              void* d_out, int out_size) {
    const float* nf   = (const float*)d_in[0];
    const float* edge = (const float*)d_in[1];
    const int*   src  = (const int*)d_in[2];
    const int*   tgt  = (const int*)d_in[3];
    const float* Wmsg = (const float*)d_in[4];
    const float* bmsg = (const float*)d_in[5];
    const float* Wih  = (const float*)d_in[6];
    const float* Whh  = (const float*)d_in[7];
    const float* bih  = (const float*)d_in[8];
    const float* bhh  = (const float*)d_in[9];
    const float* Wr1  = (const float*)d_in[10];
    const float* br1  = (const float*)d_in[11];
    const float* Wr2  = (const float*)d_in[12];
    const float* br2  = (const float*)d_in[13];
    const float* Wpol = (const float*)d_in[14];
    const float* bpol = (const float*)d_in[15];
    float* out = (float*)d_out;

    float *g_h_p, *g_bias1_p;
    __half *gh_p, *gi_p, *msg_p, *wb_p, *wih_p, *hh_p, *hl_p, *agg_p;
    cudaGetSymbolAddress((void**)&g_h_p, g_h);
    cudaGetSymbolAddress((void**)&gh_p, g_gh);
    cudaGetSymbolAddress((void**)&gi_p, g_gi);
    cudaGetSymbolAddress((void**)&g_bias1_p, g_bias1);
    cudaGetSymbolAddress((void**)&msg_p, g_msg);
    cudaGetSymbolAddress((void**)&wb_p, g_Wb);
    cudaGetSymbolAddress((void**)&wih_p, g_Wih);
    cudaGetSymbolAddress((void**)&hh_p, g_hh);
    cudaGetSymbolAddress((void**)&hl_p, g_hl);
    cudaGetSymbolAddress((void**)&agg_p, g_agg);

    cudaFuncSetAttribute((const void*)k_mm<0, 640, 1>,
                         cudaFuncAttributeMaxDynamicSharedMemorySize, MM_SMEM);
    cudaFuncSetAttribute((const void*)k_mm<1, 384, 0>,
                         cudaFuncAttributeMaxDynamicSharedMemorySize, MM_SMEM);

    // launch index 3 == first k_mm<0,640,1> (profiled)
    k_prep<<<(BB * NN * DD + 255) / 256, 256>>>(Wmsg, Whh, bhh, Wih, nf);
    k_cnt<<<CH, 256>>>(tgt);
    k_tot<<<8, 128>>>();
    k_mm<0, 640, 1><<<dim3(5, 88), 256, MM_SMEM>>>(hh_p, hl_p, wb_p, g_bias1_p,
                                                   msg_p, gh_p);
    k_scanx<<<1, NN>>>();
    k_offk<<<8, 128>>>();
    k_fill<<<CH, 32>>>(tgt, src);
    k_ef<<<(BB * EE + 255) / 256, 256>>>(edge, src, tgt);

    for (int it = 0; it < DIAM; ++it) {
        if (it > 0)
            k_mm<0, 640, 1><<<dim3(5, 88), 256, MM_SMEM>>>(hh_p, hl_p, wb_p, g_bias1_p,
                                                           msg_p, gh_p);
        k_edge<<<dim3(NN / 8, BB), 256>>>(Wmsg, bmsg);
        k_mm<1, 384, 0><<<dim3(3, 148), 256, MM_SMEM>>>(agg_p, nullptr, wih_p, bih,
                                                        nullptr, gi_p);
        k_gru<<<(BB * NN * 32 + 255) / 256, 256>>>(it == 0 ? nf : g_h_p);
    }

    k_pool<<<dim3(16, BB), 128>>>();
    k_head<<<BB, 128>>>(Wr1, br1, Wr2, br2, Wpol, bpol, out);
}